// round 3
// baseline (speedup 1.0000x reference)
#include <cuda_runtime.h>

// DentateGyrus: out = binary spike vector from Izhikevich step driven by
// injected_current = 10 * (W @ ec). Top-K over a {0,1} vector is an identity,
// so output == binary spike vector.
//
// R3: persistent single-wave (148 SMs x 4 blocks), 2 rows per warp
// (contiguous pair -> 64KB chunks, halved turnaround bubbles, 2 DRAM streams),
// __ldcs streaming loads for the one-shot W stream.

#ifndef ENTRY_DIM
#define ENTRY_DIM 8192
#endif
#define NROWS 32768
#define DTSTEP 0.5f
#define WARPS_PER_BLOCK 8
#define TPB (WARPS_PER_BLOCK * 32)
#define NUM_SMS 148
#define BLOCKS_PER_SM 4
#define GRID (NUM_SMS * BLOCKS_PER_SM)   // 592 blocks, one wave
#define NPAIRS (NROWS / 2)               // 16384

__global__ __launch_bounds__(TPB, BLOCKS_PER_SM)
void dg_gemv_spike(const float* __restrict__ ec,
                   const float* __restrict__ W,
                   const float* __restrict__ v_in,
                   const float* __restrict__ u_in,
                   float* __restrict__ out)
{
    // Stage ec (8192 f32 = 32 KB) in shared memory once per (persistent) block.
    __shared__ float4 ecs[ENTRY_DIM / 4];
    const float4* ec4 = reinterpret_cast<const float4*>(ec);
    #pragma unroll
    for (int i = threadIdx.x; i < ENTRY_DIM / 4; i += TPB) {
        ecs[i] = ec4[i];
    }
    __syncthreads();

    const int warp  = threadIdx.x >> 5;
    const int lane  = threadIdx.x & 31;
    const int gwarp = blockIdx.x * WARPS_PER_BLOCK + warp;   // 0..4735
    const int nwarp = GRID * WARPS_PER_BLOCK;                 // 4736

    for (int p = gwarp; p < NPAIRS; p += nwarp) {
        const int row0 = 2 * p;
        const float4* __restrict__ W0 =
            reinterpret_cast<const float4*>(W + (size_t)row0 * ENTRY_DIM);
        const float4* __restrict__ W1 = W0 + (ENTRY_DIM / 4);

        // 64 float4 per lane per row; two independent streams per warp.
        float a00 = 0.f, a01 = 0.f, a02 = 0.f, a03 = 0.f;
        float a10 = 0.f, a11 = 0.f, a12 = 0.f, a13 = 0.f;
        #pragma unroll 2
        for (int it = 0; it < ENTRY_DIM / 4 / 32; ++it) {
            const int idx = it * 32 + lane;
            float4 e  = ecs[idx];
            float4 w0 = __ldcs(&W0[idx]);
            float4 w1 = __ldcs(&W1[idx]);
            a00 = fmaf(w0.x, e.x, a00);
            a01 = fmaf(w0.y, e.y, a01);
            a02 = fmaf(w0.z, e.z, a02);
            a03 = fmaf(w0.w, e.w, a03);
            a10 = fmaf(w1.x, e.x, a10);
            a11 = fmaf(w1.y, e.y, a11);
            a12 = fmaf(w1.z, e.z, a12);
            a13 = fmaf(w1.w, e.w, a13);
        }
        float acc0 = (a00 + a01) + (a02 + a03);
        float acc1 = (a10 + a11) + (a12 + a13);

        #pragma unroll
        for (int off = 16; off > 0; off >>= 1) {
            acc0 += __shfl_xor_sync(0xffffffffu, acc0, off);
            acc1 += __shfl_xor_sync(0xffffffffu, acc1, off);
        }

        if (lane == 0) {
            {
                const float I  = acc0 * 10.0f;
                const float v  = v_in[row0];
                const float u  = u_in[row0];
                const float dv = 0.04f * v * v + 5.0f * v + 140.0f - u + I;
                const float vn = fmaf(dv, DTSTEP, v);
                out[row0] = (vn >= 30.0f) ? 1.0f : 0.0f;
            }
            {
                const int row1 = row0 + 1;
                const float I  = acc1 * 10.0f;
                const float v  = v_in[row1];
                const float u  = u_in[row1];
                const float dv = 0.04f * v * v + 5.0f * v + 140.0f - u + I;
                const float vn = fmaf(dv, DTSTEP, v);
                out[row1] = (vn >= 30.0f) ? 1.0f : 0.0f;
            }
        }
    }
}

extern "C" void kernel_launch(void* const* d_in, const int* in_sizes, int n_in,
                              void* d_out, int out_size)
{
    const float* ec = (const float*)d_in[0];
    const float* W  = (const float*)d_in[1];
    const float* v  = (const float*)d_in[2];
    const float* u  = (const float*)d_in[3];
    float* out = (float*)d_out;

    (void)in_sizes; (void)n_in; (void)out_size;

    dg_gemv_spike<<<GRID, TPB>>>(ec, W, v, u, out);
}

// round 5
// speedup vs baseline: 1.0333x; 1.0333x over previous
#include <cuda_runtime.h>

// DentateGyrus: out = binary spike vector from Izhikevich step driven by
// injected_current = 10 * (W @ ec). Top-K over a {0,1} vector is an identity,
// so output == binary spike vector.
//
// R5 (= R4 resubmitted; round 4 was an infra failure): R2 core (warp-per-row,
// unroll 4, default load policy) with a single change vs R2 = 5 blocks/SM
// residency (40 warps/SM, still one wave: grid = 148 * 5 = 740).
// Regs must fit 51 (5 * 256 * 51 = 65,280 <= 65,536 RF).

#ifndef ENTRY_DIM
#define ENTRY_DIM 8192
#endif
#define NROWS 32768
#define DTSTEP 0.5f
#define WARPS_PER_BLOCK 8
#define TPB (WARPS_PER_BLOCK * 32)
#define NUM_SMS 148
#define BLOCKS_PER_SM 5
#define GRID (NUM_SMS * BLOCKS_PER_SM)   // 740 blocks, one wave

__global__ __launch_bounds__(TPB, BLOCKS_PER_SM)
void dg_gemv_spike(const float* __restrict__ ec,
                   const float* __restrict__ W,
                   const float* __restrict__ v_in,
                   const float* __restrict__ u_in,
                   float* __restrict__ out)
{
    // Stage ec (8192 f32 = 32 KB) in shared memory once per (persistent) block.
    __shared__ float4 ecs[ENTRY_DIM / 4];
    const float4* ec4 = reinterpret_cast<const float4*>(ec);
    #pragma unroll
    for (int i = threadIdx.x; i < ENTRY_DIM / 4; i += TPB) {
        ecs[i] = ec4[i];
    }
    __syncthreads();

    const int warp  = threadIdx.x >> 5;
    const int lane  = threadIdx.x & 31;
    const int gwarp = blockIdx.x * WARPS_PER_BLOCK + warp;   // 0..5919
    const int nwarp = GRID * WARPS_PER_BLOCK;                 // 5920

    for (int row = gwarp; row < NROWS; row += nwarp) {
        const float4* __restrict__ Wr =
            reinterpret_cast<const float4*>(W + (size_t)row * ENTRY_DIM);

        // 64 float4 per lane, coalesced 512B warp spans, 4 loads in flight.
        float a0 = 0.f, a1 = 0.f, a2 = 0.f, a3 = 0.f;
        #pragma unroll 4
        for (int it = 0; it < ENTRY_DIM / 4 / 32; ++it) {
            float4 w = Wr[it * 32 + lane];
            float4 e = ecs[it * 32 + lane];
            a0 = fmaf(w.x, e.x, a0);
            a1 = fmaf(w.y, e.y, a1);
            a2 = fmaf(w.z, e.z, a2);
            a3 = fmaf(w.w, e.w, a3);
        }
        float acc = (a0 + a1) + (a2 + a3);

        #pragma unroll
        for (int off = 16; off > 0; off >>= 1)
            acc += __shfl_xor_sync(0xffffffffu, acc, off);

        if (lane == 0) {
            const float I  = acc * 10.0f;
            const float v  = v_in[row];
            const float u  = u_in[row];
            const float dv = 0.04f * v * v + 5.0f * v + 140.0f - u + I;
            const float vn = fmaf(dv, DTSTEP, v);
            out[row] = (vn >= 30.0f) ? 1.0f : 0.0f;
        }
    }
}

extern "C" void kernel_launch(void* const* d_in, const int* in_sizes, int n_in,
                              void* d_out, int out_size)
{
    const float* ec = (const float*)d_in[0];
    const float* W  = (const float*)d_in[1];
    const float* v  = (const float*)d_in[2];
    const float* u  = (const float*)d_in[3];
    float* out = (float*)d_out;

    (void)in_sizes; (void)n_in; (void)out_size;

    dg_gemv_spike<<<GRID, TPB>>>(ec, W, v, u, out);
}